// round 11
// baseline (speedup 1.0000x reference)
#include <cuda_runtime.h>
#include <cstdint>

// ---------------------------------------------------------------------------
// Compile-time schedule: fold the 24 CNOT permutations (GF(2)-linear) into
// the gate shuffle masks (see R9).
// ---------------------------------------------------------------------------
struct PermSched { int sh[24]; int sel[24]; int fin[16]; };

constexpr PermSched make_sched() {
    PermSched P{};
    int F[4] = {1, 2, 4, 8};
    int G[4] = {1, 2, 4, 8};
    int g = 0;
    for (int l = 0; l < 6; ++l) {
        for (int w = 0; w < 4; ++w) {
            int b = 3 - w;
            P.sh[g] = G[b];
            int S = 0;
            for (int j = 0; j < 4; ++j) S |= ((F[j] >> b) & 1) << j;
            P.sel[g] = S;
            ++g;
        }
        int r = l % 3 + 1;
        for (int w = 0; w < 4; ++w) {
            int bc = 3 - w, bt = 3 - ((w + r) & 3);
            for (int b2 = 0; b2 < 4; ++b2)
                if ((F[b2] >> bc) & 1) F[b2] ^= (1 << bt);
            G[bc] ^= G[bt];
        }
    }
    for (int k = 0; k < 16; ++k) {
        int t = 0;
        for (int b = 0; b < 4; ++b) if ((k >> b) & 1) t ^= F[b];
        P.fin[k] = t;
    }
    return P;
}
__device__ constexpr PermSched PS = make_sched();

__device__ __forceinline__ float2 cmul(float2 a, float2 b) {
    return make_float2(a.x * b.x - a.y * b.y, a.x * b.y + a.y * b.x);
}

// tf32 truncation split: hi = top 19 bits (valid tf32), lo = exact remainder
__device__ __forceinline__ float tf32_hi(float x) {
    return __uint_as_float(__float_as_uint(x) & 0xFFFFE000u);
}

// m16n8k8 tf32 warp MMA, C += A*B  (fp32 accumulate)
__device__ __forceinline__ void mma_tf32(float* c,
                                         float a0, float a1, float a2, float a3,
                                         float b0, float b1) {
    asm volatile(
        "mma.sync.aligned.m16n8k8.row.col.f32.tf32.tf32.f32 "
        "{%0,%1,%2,%3}, {%4,%5,%6,%7}, {%8,%9}, {%0,%1,%2,%3};"
        : "+f"(c[0]), "+f"(c[1]), "+f"(c[2]), "+f"(c[3])
        : "r"(__float_as_uint(a0)), "r"(__float_as_uint(a1)),
          "r"(__float_as_uint(a2)), "r"(__float_as_uint(a3)),
          "r"(__float_as_uint(b0)), "r"(__float_as_uint(b1)));
}

#define WARPS 8
#define GPW 2      // groups of 32 elements per warp

// ---------------------------------------------------------------------------
// Fused tensor-core kernel.
//   Prep (per CTA): gate matrices (threads 0..23, __sincosf) -> shared;
//   warps 0..7 propagate 16 basis columns via folded-perm shuffle butterflies
//   into sUc. Then each warp extracts its B fragments (W = [Re|Im] U columns,
//   tf32 hi/lo) once.
//   Main loop (per warp, 32 elements/group): build rank-1 state s per lane,
//   split tf32 hi/lo, stage via padded smem, load A fragments, 48 mma
//   (3 precision passes), then |t|^2 + Z-sign butterfly epilogue in 8
//   shfl-reductions per 4 elements.
// ---------------------------------------------------------------------------
__global__ __launch_bounds__(256, 2)
void qtc_kernel(const float4* __restrict__ x4, const float* __restrict__ wts,
                float4* __restrict__ out4) {
    __shared__ float2 sUc[256];            // sUc[j*16 + k] = U[k][j]
    __shared__ float2 sm[24][4];
    __shared__ float  sS[WARPS][2][32][20]; // [warp][hi/lo][elem][j] stride-20 pad

    int tid  = threadIdx.x;
    int wid  = tid >> 5;
    int lane = tid & 31;
    int gid  = lane >> 2;   // mma "groupID"
    int tid4 = lane & 3;    // mma "threadID_in_group"

    // ---- gate matrices ----
    if (tid < 24) {
        float ph = wts[tid * 3 + 0];
        float th = wts[tid * 3 + 1];
        float om = wts[tid * 3 + 2];
        float st, ct; __sincosf(0.5f * th, &st, &ct);
        float sa, ca; __sincosf(0.5f * (ph + om), &sa, &ca);
        float sb, cb; __sincosf(0.5f * (ph - om), &sb, &cb);
        sm[tid][0] = make_float2( ca * ct, -sa * ct);
        sm[tid][1] = make_float2(-cb * st, -sb * st);
        sm[tid][2] = make_float2( cb * st, -sb * st);
        sm[tid][3] = make_float2( ca * ct,  sa * ct);
    }
    __syncthreads();

    // ---- U propagation: warps 0..7, two columns per warp ----
    {
        int k   = lane & 15;
        int col = wid + ((lane >> 4) << 3);
        float2 v = make_float2(k == col ? 1.0f : 0.0f, 0.0f);
#pragma unroll
        for (int g = 0; g < 24; ++g) {
            float2 m00 = sm[g][0], m01 = sm[g][1], m10 = sm[g][2], m11 = sm[g][3];
            float px = __shfl_xor_sync(0xffffffffu, v.x, PS.sh[g]);
            float py = __shfl_xor_sync(0xffffffffu, v.y, PS.sh[g]);
            float2 p = make_float2(px, py);
            bool hi = (__popc(k & PS.sel[g]) & 1) != 0;
            float2 cv = hi ? m11 : m00;
            float2 cp = hi ? m10 : m01;
            float2 a = cmul(cv, v), b = cmul(cp, p);
            v = make_float2(a.x + b.x, a.y + b.y);
        }
        sUc[col * 16 + PS.fin[k]] = v;
    }
    __syncthreads();

    // ---- B fragments: W[j][2k+c] = (c? Im : Re) U[k][j], tf32 hi/lo ----
    // m16n8k8 B frag (col): b0 = B[row=tid4][col=gid], b1 = B[row=tid4+4][col=gid]
    float bhi[2][4][2], blo[2][4][2];
#pragma unroll
    for (int kt = 0; kt < 2; ++kt)
#pragma unroll
    for (int nt = 0; nt < 4; ++nt) {
        int gn   = nt * 8 + gid;       // global output column
        int ko   = gn >> 1;            // k index
        int comp = gn & 1;             // 0=Re, 1=Im
#pragma unroll
        for (int r = 0; r < 2; ++r) {
            int j = tid4 + r * 4 + kt * 8;   // k-dim row = s index
            float2 u = sUc[j * 16 + ko];
            float w  = comp ? u.y : u.x;
            float wh = tf32_hi(w);
            bhi[kt][nt][r] = wh;
            blo[kt][nt][r] = w - wh;
        }
    }

    int warp_global = blockIdx.x * WARPS + wid;

#pragma unroll
    for (int it = 0; it < GPW; ++it) {
        int base = (warp_global * GPW + it) * 32;

        // ---- build rank-1 state for element base+lane, stage tf32 hi/lo ----
        {
            float4 xa = x4[base + lane];
            float c0, s0, c1, s1, c2, s2, c3, s3;
            __sincosf(0.5f * xa.x, &s0, &c0);
            __sincosf(0.5f * xa.y, &s1, &c1);
            __sincosf(0.5f * xa.z, &s2, &c2);
            __sincosf(0.5f * xa.w, &s3, &c3);
            float h[4] = {c0 * c1, c0 * s1, s0 * c1, s0 * s1};
            float l[4] = {c2 * c3, c2 * s3, s2 * c3, s2 * s3};
#pragma unroll
            for (int a = 0; a < 4; ++a) {
                float v0 = h[a] * l[0], v1 = h[a] * l[1];
                float v2 = h[a] * l[2], v3 = h[a] * l[3];
                float h0 = tf32_hi(v0), h1 = tf32_hi(v1);
                float h2 = tf32_hi(v2), h3 = tf32_hi(v3);
                *(float4*)&sS[wid][0][lane][a * 4] = make_float4(h0, h1, h2, h3);
                *(float4*)&sS[wid][1][lane][a * 4] =
                    make_float4(v0 - h0, v1 - h1, v2 - h2, v3 - h3);
            }
        }
        __syncwarp();

        // ---- GEMM: C[mt][nt][4], 3 precision passes fused per k-tile ----
        float C[2][4][4];
#pragma unroll
        for (int mt = 0; mt < 2; ++mt)
#pragma unroll
            for (int nt = 0; nt < 4; ++nt)
#pragma unroll
                for (int r = 0; r < 4; ++r) C[mt][nt][r] = 0.0f;

#pragma unroll
        for (int mt = 0; mt < 2; ++mt) {
            int row0 = mt * 16 + gid, row1 = row0 + 8;
#pragma unroll
            for (int kt = 0; kt < 2; ++kt) {
                int c0i = tid4 + kt * 8, c1i = c0i + 4;
                // A frag (row-major): a0=(r0,c0) a1=(r1,c0) a2=(r0,c1) a3=(r1,c1)
                float ah0 = sS[wid][0][row0][c0i];
                float ah1 = sS[wid][0][row1][c0i];
                float ah2 = sS[wid][0][row0][c1i];
                float ah3 = sS[wid][0][row1][c1i];
                float al0 = sS[wid][1][row0][c0i];
                float al1 = sS[wid][1][row1][c0i];
                float al2 = sS[wid][1][row0][c1i];
                float al3 = sS[wid][1][row1][c1i];
#pragma unroll
                for (int nt = 0; nt < 4; ++nt) {
                    mma_tf32(C[mt][nt], ah0, ah1, ah2, ah3,
                             bhi[kt][nt][0], bhi[kt][nt][1]);
                    mma_tf32(C[mt][nt], ah0, ah1, ah2, ah3,
                             blo[kt][nt][0], blo[kt][nt][1]);
                    mma_tf32(C[mt][nt], al0, al1, al2, al3,
                             bhi[kt][nt][0], bhi[kt][nt][1]);
                }
            }
        }
        __syncwarp();   // sS free for next group

        // ---- epilogue: |t|^2 + Z-sign butterfly ----
        // lane tracks elements E[ei] = gid + 8*ei (ei = mt*2 + half)
        // C cols: global n = nt*8 + 2*tid4 (+1) -> k = nt*4 + tid4, (Re,Im)
        float o[4][4];
#pragma unroll
        for (int ei = 0; ei < 4; ++ei) {
            int mt = ei >> 1, hf = ei & 1;
            float p[4];
#pragma unroll
            for (int nt = 0; nt < 4; ++nt) {
                float re = C[mt][nt][hf * 2 + 0];
                float im = C[mt][nt][hf * 2 + 1];
                p[nt] = re * re + im * im;
            }
            float s01 = p[0] + p[1], s23 = p[2] + p[3];
            float T2  = s01 + s23;
            float q0p = s01 - s23;                 // sign by bit3 = nt>>1
            float q1p = (p[0] - p[1]) + (p[2] - p[3]);  // sign by bit2 = nt&1
            float v2  = (tid4 & 2) ? -T2 : T2;     // sign by bit1 = tid4>>1
            float v3  = (tid4 & 1) ? -T2 : T2;     // sign by bit0 = tid4&1
            q0p += __shfl_xor_sync(0xffffffffu, q0p, 1);
            q0p += __shfl_xor_sync(0xffffffffu, q0p, 2);
            q1p += __shfl_xor_sync(0xffffffffu, q1p, 1);
            q1p += __shfl_xor_sync(0xffffffffu, q1p, 2);
            v2  += __shfl_xor_sync(0xffffffffu, v2, 1);
            v2  += __shfl_xor_sync(0xffffffffu, v2, 2);
            v3  += __shfl_xor_sync(0xffffffffu, v3, 1);
            v3  += __shfl_xor_sync(0xffffffffu, v3, 2);
            o[ei][0] = q0p; o[ei][1] = q1p; o[ei][2] = v2; o[ei][3] = v3;
        }

        // lane tid4 stores element gid + 8*tid4 (its o[tid4])
        float4 ov = make_float4(o[0][0], o[0][1], o[0][2], o[0][3]);
        if (tid4 == 1) ov = make_float4(o[1][0], o[1][1], o[1][2], o[1][3]);
        if (tid4 == 2) ov = make_float4(o[2][0], o[2][1], o[2][2], o[2][3]);
        if (tid4 == 3) ov = make_float4(o[3][0], o[3][1], o[3][2], o[3][3]);
        out4[base + gid + 8 * tid4] = ov;
    }
}

extern "C" void kernel_launch(void* const* d_in, const int* in_sizes, int n_in,
                              void* d_out, int out_size) {
    const float* x   = (const float*)d_in[0];
    const float* wts = (const float*)d_in[1];
    int nx = in_sizes[0];
    if (n_in >= 2 && in_sizes[0] == 72 && in_sizes[1] != 72) {
        wts = (const float*)d_in[0];
        x   = (const float*)d_in[1];
        nx  = in_sizes[1];
    }
    int B = nx / 4;                       // 262144
    int groups = B / 32;                  // 8192
    int warps  = groups / GPW;            // 4096
    int grid   = warps / WARPS;           // 512

    qtc_kernel<<<grid, 256>>>((const float4*)x, wts, (float4*)d_out);
}

// round 12
// speedup vs baseline: 1.1955x; 1.1955x over previous
#include <cuda_runtime.h>
#include <cstdint>

// ---------------------------------------------------------------------------
// Compile-time schedule: fold the 24 CNOT permutations (GF(2)-linear) into
// the gate shuffle masks (see R9).
// ---------------------------------------------------------------------------
struct PermSched { int sh[24]; int sel[24]; int fin[16]; };

constexpr PermSched make_sched() {
    PermSched P{};
    int F[4] = {1, 2, 4, 8};
    int G[4] = {1, 2, 4, 8};
    int g = 0;
    for (int l = 0; l < 6; ++l) {
        for (int w = 0; w < 4; ++w) {
            int b = 3 - w;
            P.sh[g] = G[b];
            int S = 0;
            for (int j = 0; j < 4; ++j) S |= ((F[j] >> b) & 1) << j;
            P.sel[g] = S;
            ++g;
        }
        int r = l % 3 + 1;
        for (int w = 0; w < 4; ++w) {
            int bc = 3 - w, bt = 3 - ((w + r) & 3);
            for (int b2 = 0; b2 < 4; ++b2)
                if ((F[b2] >> bc) & 1) F[b2] ^= (1 << bt);
            G[bc] ^= G[bt];
        }
    }
    for (int k = 0; k < 16; ++k) {
        int t = 0;
        for (int b = 0; b < 4; ++b) if ((k >> b) & 1) t ^= F[b];
        P.fin[k] = t;
    }
    return P;
}
__device__ constexpr PermSched PS = make_sched();

__device__ __forceinline__ float2 cmul(float2 a, float2 b) {
    return make_float2(a.x * b.x - a.y * b.y, a.x * b.y + a.y * b.x);
}

// tf32 truncation split: hi = top 19 bits (valid tf32), lo = exact remainder
__device__ __forceinline__ float tf32_hi(float x) {
    return __uint_as_float(__float_as_uint(x) & 0xFFFFE000u);
}

// m16n8k8 tf32 warp MMA, C += A*B  (fp32 accumulate)
__device__ __forceinline__ void mma_tf32(float* c,
                                         float a0, float a1, float a2, float a3,
                                         float b0, float b1) {
    asm volatile(
        "mma.sync.aligned.m16n8k8.row.col.f32.tf32.tf32.f32 "
        "{%0,%1,%2,%3}, {%4,%5,%6,%7}, {%8,%9}, {%0,%1,%2,%3};"
        : "+f"(c[0]), "+f"(c[1]), "+f"(c[2]), "+f"(c[3])
        : "r"(__float_as_uint(a0)), "r"(__float_as_uint(a1)),
          "r"(__float_as_uint(a2)), "r"(__float_as_uint(a3)),
          "r"(__float_as_uint(b0)), "r"(__float_as_uint(b1)));
}

#define WARPS 8
#define GPW 4      // groups of 32 elements per warp

// ---------------------------------------------------------------------------
// Fused tensor-core kernel, zero-staging A fragments.
//   Prep (per CTA): gate matrices -> shared; warps 0..7 propagate 16 basis
//   columns via folded-perm shuffle butterflies into sUc; each warp extracts
//   its B fragments (W = [Re|Im]U, tf32 hi/lo) once.
//   Main loop: lane (gid,tid4) owns elements gid+8m (m=0..3) of its group.
//   A-frag values are s_j(elem) with j = tid4+4t, and s_j = h[t]*l[tid4] --
//   so the lane computes its fragments directly from x (no smem staging,
//   no syncwarp). 48 mma (3-pass tf32 hi/lo), then |t|^2 + Z-sign butterfly
//   (7 shfl per 4 elements) and direct store of the 4 owned elements.
// ---------------------------------------------------------------------------
__global__ __launch_bounds__(256, 2)
void qtc_kernel(const float4* __restrict__ x4, const float* __restrict__ wts,
                float4* __restrict__ out4) {
    __shared__ float2 sUc[256];    // sUc[j*16 + k] = U[k][j]
    __shared__ float2 sm[24][4];

    int tid  = threadIdx.x;
    int wid  = tid >> 5;
    int lane = tid & 31;
    int gid  = lane >> 2;   // mma "groupID"
    int tid4 = lane & 3;    // mma "threadID_in_group"

    // ---- gate matrices ----
    if (tid < 24) {
        float ph = wts[tid * 3 + 0];
        float th = wts[tid * 3 + 1];
        float om = wts[tid * 3 + 2];
        float st, ct; __sincosf(0.5f * th, &st, &ct);
        float sa, ca; __sincosf(0.5f * (ph + om), &sa, &ca);
        float sb, cb; __sincosf(0.5f * (ph - om), &sb, &cb);
        sm[tid][0] = make_float2( ca * ct, -sa * ct);
        sm[tid][1] = make_float2(-cb * st, -sb * st);
        sm[tid][2] = make_float2( cb * st, -sb * st);
        sm[tid][3] = make_float2( ca * ct,  sa * ct);
    }
    __syncthreads();

    // ---- U propagation: warps 0..7, two columns per warp ----
    {
        int k   = lane & 15;
        int col = wid + ((lane >> 4) << 3);
        float2 v = make_float2(k == col ? 1.0f : 0.0f, 0.0f);
#pragma unroll
        for (int g = 0; g < 24; ++g) {
            float2 m00 = sm[g][0], m01 = sm[g][1], m10 = sm[g][2], m11 = sm[g][3];
            float px = __shfl_xor_sync(0xffffffffu, v.x, PS.sh[g]);
            float py = __shfl_xor_sync(0xffffffffu, v.y, PS.sh[g]);
            float2 p = make_float2(px, py);
            bool hi = (__popc(k & PS.sel[g]) & 1) != 0;
            float2 cv = hi ? m11 : m00;
            float2 cp = hi ? m10 : m01;
            float2 a = cmul(cv, v), b = cmul(cp, p);
            v = make_float2(a.x + b.x, a.y + b.y);
        }
        sUc[col * 16 + PS.fin[k]] = v;
    }
    __syncthreads();

    // ---- B fragments: W[j][2k+c] = (c? Im : Re) U[k][j], tf32 hi/lo ----
    float bhi[2][4][2], blo[2][4][2];
#pragma unroll
    for (int kt = 0; kt < 2; ++kt)
#pragma unroll
    for (int nt = 0; nt < 4; ++nt) {
        int gn   = nt * 8 + gid;       // global output column
        int ko   = gn >> 1;            // k index
        int comp = gn & 1;             // 0=Re, 1=Im
#pragma unroll
        for (int r = 0; r < 2; ++r) {
            int j = tid4 + r * 4 + kt * 8;
            float2 u = sUc[j * 16 + ko];
            float w  = comp ? u.y : u.x;
            float wh = tf32_hi(w);
            bhi[kt][nt][r] = wh;
            blo[kt][nt][r] = w - wh;
        }
    }

    int warp_global = blockIdx.x * WARPS + wid;

#pragma unroll
    for (int it = 0; it < GPW; ++it) {
        int base = (warp_global * GPW + it) * 32;

        // ---- A fragments computed directly: Ahi/Alo[m][t] = split of
        //      s_{tid4+4t}(element gid+8m) = h[t](elem) * l[tid4](elem) ----
        float Ahi[4][4], Alo[4][4];
#pragma unroll
        for (int m = 0; m < 4; ++m) {
            float4 xa = x4[base + gid + 8 * m];
            float c0, s0, c1, s1, c2, s2, c3, s3;
            __sincosf(0.5f * xa.x, &s0, &c0);
            __sincosf(0.5f * xa.y, &s1, &c1);
            __sincosf(0.5f * xa.z, &s2, &c2);
            __sincosf(0.5f * xa.w, &s3, &c3);
            float h0 = c0 * c1, h1 = c0 * s1, h2 = s0 * c1, h3 = s0 * s1;
            float lv = ((tid4 & 2) ? s2 : c2) * ((tid4 & 1) ? s3 : c3);
            float v0 = h0 * lv, v1 = h1 * lv, v2 = h2 * lv, v3 = h3 * lv;
            float w0 = tf32_hi(v0), w1 = tf32_hi(v1);
            float w2 = tf32_hi(v2), w3 = tf32_hi(v3);
            Ahi[m][0] = w0; Ahi[m][1] = w1; Ahi[m][2] = w2; Ahi[m][3] = w3;
            Alo[m][0] = v0 - w0; Alo[m][1] = v1 - w1;
            Alo[m][2] = v2 - w2; Alo[m][3] = v3 - w3;
        }

        // ---- GEMM: 48 mma, 3 precision passes ----
        float C[2][4][4];
#pragma unroll
        for (int mt = 0; mt < 2; ++mt)
#pragma unroll
            for (int nt = 0; nt < 4; ++nt)
#pragma unroll
                for (int r = 0; r < 4; ++r) C[mt][nt][r] = 0.0f;

#pragma unroll
        for (int mt = 0; mt < 2; ++mt) {
#pragma unroll
            for (int kt = 0; kt < 2; ++kt) {
                // A frag: a0=(row0,c0) a1=(row1,c0) a2=(row0,c1) a3=(row1,c1)
                // row0 -> element m=2mt, row1 -> m=2mt+1; c0 -> t=2kt, c1 -> t=2kt+1
                float ah0 = Ahi[2 * mt][2 * kt];
                float ah1 = Ahi[2 * mt + 1][2 * kt];
                float ah2 = Ahi[2 * mt][2 * kt + 1];
                float ah3 = Ahi[2 * mt + 1][2 * kt + 1];
                float al0 = Alo[2 * mt][2 * kt];
                float al1 = Alo[2 * mt + 1][2 * kt];
                float al2 = Alo[2 * mt][2 * kt + 1];
                float al3 = Alo[2 * mt + 1][2 * kt + 1];
#pragma unroll
                for (int nt = 0; nt < 4; ++nt) {
                    mma_tf32(C[mt][nt], ah0, ah1, ah2, ah3,
                             bhi[kt][nt][0], bhi[kt][nt][1]);
                    mma_tf32(C[mt][nt], ah0, ah1, ah2, ah3,
                             blo[kt][nt][0], blo[kt][nt][1]);
                    mma_tf32(C[mt][nt], al0, al1, al2, al3,
                             bhi[kt][nt][0], bhi[kt][nt][1]);
                }
            }
        }

        // ---- epilogue: |t|^2 + Z-sign butterfly (7 shfl per ei) ----
        // element of ei = gid + 8*ei (ei = mt*2 + half); k = nt*4 + tid4
        float o[4][4];
#pragma unroll
        for (int ei = 0; ei < 4; ++ei) {
            int mt = ei >> 1, hf = ei & 1;
            float p[4];
#pragma unroll
            for (int nt = 0; nt < 4; ++nt) {
                float re = C[mt][nt][hf * 2 + 0];
                float im = C[mt][nt][hf * 2 + 1];
                p[nt] = re * re + im * im;
            }
            float s01 = p[0] + p[1], s23 = p[2] + p[3];
            float T2  = s01 + s23;
            float q0p = s01 - s23;                       // sign bit3 (nt>>1)
            float q1p = (p[0] - p[1]) + (p[2] - p[3]);   // sign bit2 (nt&1)
            // reduce q0p, q1p over tid4 group
            q0p += __shfl_xor_sync(0xffffffffu, q0p, 1);
            q0p += __shfl_xor_sync(0xffffffffu, q0p, 2);
            q1p += __shfl_xor_sync(0xffffffffu, q1p, 1);
            q1p += __shfl_xor_sync(0xffffffffu, q1p, 2);
            // v2 (sign bit1 = tid4>>1), v3 (sign bit0 = tid4&1) from T2: 3 shfl
            float x1 = __shfl_xor_sync(0xffffffffu, T2, 1);
            float sfull = T2 + x1;
            float d = (tid4 & 1) ? (x1 - T2) : (T2 - x1);   // T2_even - T2_odd
            float m2 = __shfl_xor_sync(0xffffffffu, sfull, 2);
            float v2 = (tid4 & 2) ? (m2 - sfull) : (sfull - m2);
            float d2 = __shfl_xor_sync(0xffffffffu, d, 2);
            float v3 = d + d2;
            o[ei][0] = q0p; o[ei][1] = q1p; o[ei][2] = v2; o[ei][3] = v3;
        }

        // lane tid4 stores its element gid + 8*tid4
        float4 ov = make_float4(o[0][0], o[0][1], o[0][2], o[0][3]);
        if (tid4 == 1) ov = make_float4(o[1][0], o[1][1], o[1][2], o[1][3]);
        if (tid4 == 2) ov = make_float4(o[2][0], o[2][1], o[2][2], o[2][3]);
        if (tid4 == 3) ov = make_float4(o[3][0], o[3][1], o[3][2], o[3][3]);
        out4[base + gid + 8 * tid4] = ov;
    }
}

extern "C" void kernel_launch(void* const* d_in, const int* in_sizes, int n_in,
                              void* d_out, int out_size) {
    const float* x   = (const float*)d_in[0];
    const float* wts = (const float*)d_in[1];
    int nx = in_sizes[0];
    if (n_in >= 2 && in_sizes[0] == 72 && in_sizes[1] != 72) {
        wts = (const float*)d_in[0];
        x   = (const float*)d_in[1];
        nx  = in_sizes[1];
    }
    int B = nx / 4;                       // 262144
    int groups = B / 32;                  // 8192
    int warps  = groups / GPW;            // 2048
    int grid   = warps / WARPS;           // 256

    qtc_kernel<<<grid, 256>>>((const float4*)x, wts, (float4*)d_out);
}